// round 10
// baseline (speedup 1.0000x reference)
#include <cuda_runtime.h>
#include <cuda_fp16.h>
#include <math.h>
#include <stdint.h>

#define BB 2048
#define KK 256
#define AD 512
#define IN 768

// GEMM tiling: 64x64 CTA tile, 128 threads (4 warps, 32x32 each)
#define TM 64
#define TN 64
#define TKC 64                     // K-chunk (fp16 elems) = 128 B/row
#define NSTAGE 3
#define A_ST_B (TM * 128)
#define B_ST_B (TN * 128)
#define GEMM_SMEM (NSTAGE * (A_ST_B + B_ST_B))   // 49152 B

// ---------------- scratch (device globals: no allocs allowed) ----------------
// 2-term fp16 split: A-side [hi|lo], B-side [hi|hi]  (computes a . b_hi)
__device__ __half g_A1  [(size_t)BB * 1536];   // split concat(E,H,Q)
__device__ __half g_W1s [(size_t)AD * 1536];   // split W1
__device__ __half g_A2  [(size_t)BB * 1024];   // split X (G1 out)
__device__ __half g_B2p [(size_t)768 * 1024];  // G2' B: rows 0-255 = W2[256:512] split; 256-767 = W3' split
__device__ __half g_W2T2[(size_t)512 * 512];   // prep B: W2[:256,:]^T split [hi|hi] (K'=512)
__device__ __half g_Er2 [(size_t)512 * 512];   // prep A: emb_r split [hi|lo]  (K'=512)
__device__ float  g_bias2p[768];               // [0:256]=b2[256:512], [256:768]=bias3
__device__ float  g_X2e[(size_t)BB * 256];     // X2[:, 256:512] fp32
__device__ float  g_P  [(size_t)BB * 512];     // P = X @ W3'^T + bias3

// ---------------- helpers ----------------
__device__ __forceinline__ uint32_t smem_u32(const void* p) {
    uint32_t a;
    asm("{ .reg .u64 t; cvta.to.shared.u64 t, %1; cvt.u32.u64 %0, t; }" : "=r"(a) : "l"(p));
    return a;
}
#define CP_ASYNC16(dst, src) \
    asm volatile("cp.async.cg.shared.global [%0], [%1], 16;" :: "r"(dst), "l"(src) : "memory")
#define CP_COMMIT()  asm volatile("cp.async.commit_group;" ::: "memory")
#define CP_WAIT(n)   asm volatile("cp.async.wait_group %0;" :: "n"(n) : "memory")

__device__ __forceinline__ void ldsm_x4(uint32_t* r, uint32_t addr) {
    asm volatile("ldmatrix.sync.aligned.m8n8.x4.shared.b16 {%0,%1,%2,%3}, [%4];"
                 : "=r"(r[0]), "=r"(r[1]), "=r"(r[2]), "=r"(r[3]) : "r"(addr));
}
__device__ __forceinline__ void mma16816(float* c, const uint32_t* a, const uint32_t* b) {
    asm volatile(
        "mma.sync.aligned.m16n8k16.row.col.f32.f16.f16.f32 "
        "{%0,%1,%2,%3}, {%4,%5,%6,%7}, {%8,%9}, {%0,%1,%2,%3};"
        : "+f"(c[0]), "+f"(c[1]), "+f"(c[2]), "+f"(c[3])
        : "r"(a[0]), "r"(a[1]), "r"(a[2]), "r"(a[3]), "r"(b[0]), "r"(b[1]));
}
// 256-bit evict_last gather (required vector width for L2::evict_last on sm_103)
__device__ __forceinline__ void ldg_el8(float4& a, float4& b, const float* p) {
    asm volatile("ld.global.nc.L2::evict_last.v8.b32 {%0,%1,%2,%3,%4,%5,%6,%7}, [%8];"
                 : "=f"(a.x), "=f"(a.y), "=f"(a.z), "=f"(a.w),
                   "=f"(b.x), "=f"(b.y), "=f"(b.z), "=f"(b.w)
                 : "l"(p));
}

__device__ __forceinline__ uint32_t swz(int row, int seg) {
    return (uint32_t)(row * 128 + ((seg ^ (row & 7)) << 4));
}

__device__ __forceinline__ void split_store_A(float4 v, __half* d, int Koff) {
    __align__(8) __half hh[4], ll[4];
    hh[0] = __float2half_rn(v.x); ll[0] = __float2half_rn(v.x - __half2float(hh[0]));
    hh[1] = __float2half_rn(v.y); ll[1] = __float2half_rn(v.y - __half2float(hh[1]));
    hh[2] = __float2half_rn(v.z); ll[2] = __float2half_rn(v.z - __half2float(hh[2]));
    hh[3] = __float2half_rn(v.w); ll[3] = __float2half_rn(v.w - __half2float(hh[3]));
    *(uint2*)d          = *(uint2*)hh;
    *(uint2*)(d + Koff) = *(uint2*)ll;
}
__device__ __forceinline__ void split_store_B(float4 v, __half* d, int Koff) {
    __align__(8) __half hh[4];
    hh[0] = __float2half_rn(v.x); hh[1] = __float2half_rn(v.y);
    hh[2] = __float2half_rn(v.z); hh[3] = __float2half_rn(v.w);
    *(uint2*)d          = *(uint2*)hh;
    *(uint2*)(d + Koff) = *(uint2*)hh;
}

// ---------------- fused conversion kernel ----------------
// R0: A1 (BB x 768) A-split         R1: W1s (512 x 768) B-split
// R2: B2p rows 0-255 <- W2[256:512] B-split
// R3: W2T2 <- W2[:256,:]^T B-split  R4: Er2 <- emb_r A-split (rows>=500 zero)
// R5: bias2p[0:256] <- b2[256:512]
#define QR0 (BB * IN / 4)            // 393216
#define QR1 (QR0 + 512 * 768 / 4)    // 491520
#define QR2 (QR1 + 256 * 512 / 4)    // 524288
#define QR3 (QR2 + 512 * 64)         // 557056
#define QR4 (QR3 + 512 * 64)         // 589824
#define QTOT (QR4 + 64)              // 589888

__global__ __launch_bounds__(256) void conv_all(
    const float* __restrict__ E, const float* __restrict__ H, const float* __restrict__ Qm,
    const float* __restrict__ W1, const float* __restrict__ W2, const float* __restrict__ emb_r,
    const float* __restrict__ b2,
    __half* __restrict__ A1, __half* __restrict__ W1s, __half* __restrict__ B2p,
    __half* __restrict__ W2T2, __half* __restrict__ Er2, float* __restrict__ bias2p)
{
    const int q = blockIdx.x * 256 + threadIdx.x;
    if (q >= QTOT) return;
    if (q < QR0) {
        const int m = q / 192, c = (q % 192) * 4;
        const float* src = (c < 256) ? (E + m * 256 + c)
                         : (c < 512) ? (H + m * 256 + (c - 256))
                                     : (Qm + m * 256 + (c - 512));
        float4 v = *(const float4*)src;
        split_store_A(v, A1 + (size_t)m * 1536 + c, 768);
    } else if (q < QR1) {
        const int q2 = q - QR0;
        const int n = q2 / 192, k = (q2 % 192) * 4;
        float4 v = *(const float4*)(W1 + (size_t)n * 768 + k);
        split_store_B(v, W1s + (size_t)n * 1536 + k, 768);
    } else if (q < QR2) {
        const int q2 = q - QR1;
        const int n = q2 >> 7, k = (q2 & 127) * 4;           // n 0..255 -> W2 row 256+n
        float4 v = *(const float4*)(W2 + (size_t)(256 + n) * 512 + k);
        split_store_B(v, B2p + (size_t)n * 1024 + k, 512);
    } else if (q < QR3) {
        const int q2 = q - QR2;
        const int d = q2 >> 6, c0 = (q2 & 63) * 4;           // W2T2[d, c] = W2[c, d], c<256
        float4 v;
        v.x = W2[(size_t)(c0 + 0) * 512 + d];
        v.y = W2[(size_t)(c0 + 1) * 512 + d];
        v.z = W2[(size_t)(c0 + 2) * 512 + d];
        v.w = W2[(size_t)(c0 + 3) * 512 + d];
        split_store_B(v, W2T2 + (size_t)d * 512 + c0, 256);
    } else if (q < QR4) {
        const int q2 = q - QR3;
        const int n = q2 >> 6, k = (q2 & 63) * 4;            // emb_r rows, pad >=500
        float4 v = make_float4(0.f, 0.f, 0.f, 0.f);
        if (n < 500) v = *(const float4*)(emb_r + (size_t)n * 256 + k);
        split_store_A(v, Er2 + (size_t)n * 512 + k, 256);
    } else {
        const int q2 = q - QR4;                               // 64 quads of b2[256:512]
        float4 v = *(const float4*)(b2 + 256 + q2 * 4);
        *(float4*)(bias2p + q2 * 4) = v;
    }
}

// ---------------- HMMA GEMM ----------------
// MODE 0 (G1):   +b1, relu, A-split store to g_A2 (W=512)
// MODE 1 (G2'):  +bias2p; cols<256 -> fp32 g_X2e; cols>=256 -> fp32 g_P
// MODE 3 (prep): B-split store to g_B2p rows 256+; n0==0 CTAs also compute bias3
template <int MODE>
__global__ __launch_bounds__(128) void gemm_mma(
    const __half* __restrict__ A, const __half* __restrict__ Bm,
    int ldk, int nchunks, const float* __restrict__ bias,
    __half* __restrict__ outs, float* __restrict__ outf, float* __restrict__ outf2,
    const float* __restrict__ erf, const float* __restrict__ b2f, float* __restrict__ bias3out)
{
    extern __shared__ __half sm[];
    const uint32_t smA = smem_u32(sm);
    const uint32_t smB = smA + NSTAGE * A_ST_B;

    const int t = threadIdx.x;
    const int warp = t >> 5, lane = t & 31;
    const int m0 = blockIdx.x * TM;
    const int n0 = blockIdx.y * TN;
    const int wm = (warp >> 1) * 32;
    const int wn = (warp & 1) * 32;

    const int rA  = lane & 15;
    const int sA8 = (lane >> 4);
    const int rB  = (lane & 7) + ((lane >> 4) & 1) * 8;
    const int sB8 = ((lane >> 3) & 1);

    float acc[2][4][4] = {};

    auto load_stage = [&](int s, int chunk) {
        const size_t k0 = (size_t)chunk * TKC;
        const uint32_t dA = smA + s * A_ST_B;
        const uint32_t dB = smB + s * B_ST_B;
        #pragma unroll
        for (int i = 0; i < 4; i++) {
            int v = t + i * 128;
            int row = v >> 3, seg = v & 7;
            CP_ASYNC16(dA + swz(row, seg),
                       A + (size_t)(m0 + row) * ldk + k0 + seg * 8);
        }
        #pragma unroll
        for (int i = 0; i < 4; i++) {
            int v = t + i * 128;
            int row = v >> 3, seg = v & 7;
            CP_ASYNC16(dB + swz(row, seg),
                       Bm + (size_t)(n0 + row) * ldk + k0 + seg * 8);
        }
        CP_COMMIT();
    };

    load_stage(0, 0);
    load_stage(1, 1);

    for (int i = 0; i < nchunks; i++) {
        CP_WAIT(1);
        __syncthreads();
        if (i + 2 < nchunks) load_stage((i + 2) % NSTAGE, i + 2);
        else CP_COMMIT();

        const uint32_t sAst = smA + (i % NSTAGE) * A_ST_B;
        const uint32_t sBst = smB + (i % NSTAGE) * B_ST_B;
        #pragma unroll
        for (int ks = 0; ks < 4; ks++) {
            uint32_t a0[4], a1[4], b0[4], b1[4];
            const int segK = ks * 2;
            ldsm_x4(a0, sAst + swz(wm +      rA, segK + sA8));
            ldsm_x4(a1, sAst + swz(wm + 16 + rA, segK + sA8));
            ldsm_x4(b0, sBst + swz(wn +      rB, segK + sB8));
            ldsm_x4(b1, sBst + swz(wn + 16 + rB, segK + sB8));
            #pragma unroll
            for (int mi = 0; mi < 2; mi++) {
                const uint32_t* aa = mi ? a1 : a0;
                mma16816(acc[mi][0], aa, b0 + 0);
                mma16816(acc[mi][1], aa, b0 + 2);
                mma16816(acc[mi][2], aa, b1 + 0);
                mma16816(acc[mi][3], aa, b1 + 2);
            }
        }
    }

    // ---------------- epilogue ----------------
    #pragma unroll
    for (int mi = 0; mi < 2; mi++) {
        #pragma unroll
        for (int h = 0; h < 2; h++) {
            const int row = m0 + wm + 16 * mi + 8 * h + (lane >> 2);
            #pragma unroll
            for (int j = 0; j < 4; j++) {
                const int col = n0 + wn + 8 * j + 2 * (lane & 3);
                float v0 = acc[mi][j][2 * h];
                float v1 = acc[mi][j][2 * h + 1];
                if (MODE == 0) {
                    v0 = fmaxf(v0 + __ldg(&bias[col]), 0.0f);
                    v1 = fmaxf(v1 + __ldg(&bias[col + 1]), 0.0f);
                    __half h0 = __float2half_rn(v0);
                    __half h1 = __float2half_rn(v1);
                    __half l0 = __float2half_rn(v0 - __half2float(h0));
                    __half l1 = __float2half_rn(v1 - __half2float(h1));
                    __half2 hh; hh.x = h0; hh.y = h1;
                    __half2 ll; ll.x = l0; ll.y = l1;
                    __half* r0 = outs + (size_t)row * 1024 + col;
                    *(__half2*)(r0)       = hh;
                    *(__half2*)(r0 + 512) = ll;
                } else if (MODE == 1) {
                    v0 += __ldg(&bias[col]);
                    v1 += __ldg(&bias[col + 1]);
                    if (col < 256)
                        *(float2*)(outf + (size_t)row * 256 + col) = make_float2(v0, v1);
                    else
                        *(float2*)(outf2 + (size_t)row * 512 + (col - 256)) = make_float2(v0, v1);
                } else {   // MODE 3: prep -> B2p rows 256+row, [hi|hi]
                    __half2 hh;
                    hh.x = __float2half_rn(v0);
                    hh.y = __float2half_rn(v1);
                    __half* r0 = outs + (size_t)(256 + row) * 1024 + col;
                    *(__half2*)(r0)       = hh;
                    *(__half2*)(r0 + 512) = hh;
                }
            }
        }
    }

    if (MODE == 3 && n0 == 0) {       // bias3[j] = <emb_r[j,:256], b2[:256]>
        const int j = m0 + (t >> 1);
        const int half = t & 1;
        float s = 0.0f;
        if (j < 500) {
            const float* er = erf + (size_t)j * 256 + half * 128;
            const float* bb = b2f + half * 128;
            #pragma unroll 4
            for (int c = 0; c < 128; c++) s += er[c] * bb[c];
        }
        s += __shfl_xor_sync(0xFFFFFFFFu, s, 1);
        if (half == 0) bias3out[256 + j] = (j < 500) ? s : 0.0f;
    }
}

// ---------------- score + softmax + entropy (mask-skipped, 256b evict_last gather) ----------------
__global__ __launch_bounds__(256) void score_softmax(
    const float* __restrict__ X2e, const float* __restrict__ P,
    const float* __restrict__ emb_e, const float* __restrict__ mask,
    const int* __restrict__ r_space, const int* __restrict__ e_space,
    float* __restrict__ out_dist, float* __restrict__ out_ent, int write_ent)
{
    const int b = blockIdx.x;
    __shared__ float x2e[256];
    __shared__ float sc[KK];
    __shared__ float red1[8], red2[8], red3[8];
    const int t = threadIdx.x;
    const int warp = t >> 5, lane = t & 31;

    x2e[t] = X2e[b * 256 + t];
    const int   kidx = warp * 32 + lane;
    const int   eall = e_space[b * KK + kidx];
    const float mval = mask[b * KK + kidx];
    const unsigned validb = __ballot_sync(0xFFFFFFFFu, mval != 0.0f);
    __syncthreads();

    // lane owns elements [lane*8, lane*8+8) of the 256-elem dot
    const float4 xa = *(const float4*)&x2e[lane * 8];
    const float4 xb = *(const float4*)&x2e[lane * 8 + 4];

    for (int i = 0; i < 32; i++) {
        const int k = warp * 32 + i;
        if ((validb >> i) & 1u) {
            const int e = __shfl_sync(0xFFFFFFFFu, eall, i);
            float4 v0, v1;
            ldg_el8(v0, v1, emb_e + (size_t)e * 256 + lane * 8);
            float s = v0.x * xa.x + v0.y * xa.y + v0.z * xa.z + v0.w * xa.w
                    + v1.x * xb.x + v1.y * xb.y + v1.z * xb.z + v1.w * xb.w;
            #pragma unroll
            for (int o = 16; o; o >>= 1) s += __shfl_xor_sync(0xFFFFFFFFu, s, o);
            if (lane == 0) sc[k] = s;
        } else {
            if (lane == 0) sc[k] = 0.0f;
        }
    }
    __syncthreads();

    const int r = r_space[b * KK + t];
    float s = sc[t] + P[b * 512 + r] - (1.0f - mask[b * KK + t]) * 1e31f;

    float mx = s;
#pragma unroll
    for (int o = 16; o; o >>= 1) mx = fmaxf(mx, __shfl_xor_sync(0xFFFFFFFFu, mx, o));
    if (lane == 0) red1[warp] = mx;
    __syncthreads();
    float bm = red1[0];
#pragma unroll
    for (int w = 1; w < 8; w++) bm = fmaxf(bm, red1[w]);

    const float p = expf(s - bm);
    float sum = p;
#pragma unroll
    for (int o = 16; o; o >>= 1) sum += __shfl_xor_sync(0xFFFFFFFFu, sum, o);
    if (lane == 0) red2[warp] = sum;
    __syncthreads();
    float bs = 0.f;
#pragma unroll
    for (int w = 0; w < 8; w++) bs += red2[w];

    const float dist = p / bs;
    out_dist[b * KK + t] = dist;

    float es = -dist * logf(dist + 1e-20f);
#pragma unroll
    for (int o = 16; o; o >>= 1) es += __shfl_xor_sync(0xFFFFFFFFu, es, o);
    if (lane == 0) red3[warp] = es;
    __syncthreads();
    if (t == 0 && write_ent) {
        float tot = 0.f;
#pragma unroll
        for (int w = 0; w < 8; w++) tot += red3[w];
        out_ent[b] = tot;
    }
}

// ---------------- launcher ----------------
extern "C" void kernel_launch(void* const* d_in, const int* in_sizes, int n_in,
                              void* d_out, int out_size)
{
    const float* E     = (const float*)d_in[0];
    const float* H     = (const float*)d_in[1];
    const float* Q     = (const float*)d_in[2];
    const float* W1    = (const float*)d_in[3];
    const float* b1    = (const float*)d_in[4];
    const float* W2    = (const float*)d_in[5];
    const float* b2    = (const float*)d_in[6];
    const float* emb_r = (const float*)d_in[7];
    const float* emb_e = (const float*)d_in[8];
    const float* mask  = (const float*)d_in[9];
    const int*   r_sp  = (const int*)d_in[10];
    const int*   e_sp  = (const int*)d_in[11];
    float* out = (float*)d_out;

    __half *gA1, *gW1s, *gA2, *gB2p, *gW2T2, *gEr2;
    float *gX2e, *gP, *gbias2p;
    cudaGetSymbolAddress((void**)&gA1,    g_A1);
    cudaGetSymbolAddress((void**)&gW1s,   g_W1s);
    cudaGetSymbolAddress((void**)&gA2,    g_A2);
    cudaGetSymbolAddress((void**)&gB2p,   g_B2p);
    cudaGetSymbolAddress((void**)&gW2T2,  g_W2T2);
    cudaGetSymbolAddress((void**)&gEr2,   g_Er2);
    cudaGetSymbolAddress((void**)&gX2e,   g_X2e);
    cudaGetSymbolAddress((void**)&gP,     g_P);
    cudaGetSymbolAddress((void**)&gbias2p, g_bias2p);

    cudaFuncSetAttribute(gemm_mma<0>, cudaFuncAttributeMaxDynamicSharedMemorySize, GEMM_SMEM);
    cudaFuncSetAttribute(gemm_mma<1>, cudaFuncAttributeMaxDynamicSharedMemorySize, GEMM_SMEM);
    cudaFuncSetAttribute(gemm_mma<3>, cudaFuncAttributeMaxDynamicSharedMemorySize, GEMM_SMEM);

    const int write_ent = (out_size >= BB * KK + BB) ? 1 : 0;

    conv_all<<<(QTOT + 255) / 256, 256>>>(E, H, Q, W1, W2, emb_r, b2,
                                          gA1, gW1s, gB2p, gW2T2, gEr2, gbias2p);

    // prep: W3' = emb_r @ W2[:256,:]  -> B2p rows 256..767  (+ bias3)
    gemm_mma<3><<<dim3(8, 8), 128, GEMM_SMEM>>>(gEr2, gW2T2, 512, 8, nullptr,
                                                gB2p, nullptr, nullptr,
                                                emb_r, b2, gbias2p);
    // G1: X = relu(A1 @ W1^T + b1)
    gemm_mma<0><<<dim3(32, 8), 128, GEMM_SMEM>>>(gA1, gW1s, 1536, 24, b1,
                                                 gA2, nullptr, nullptr,
                                                 nullptr, nullptr, nullptr);
    // G2': [X2e | P] = X @ [W2[256:]; W3']^T + bias2p
    gemm_mma<1><<<dim3(32, 12), 128, GEMM_SMEM>>>(gA2, gB2p, 1024, 16, gbias2p,
                                                  nullptr, gX2e, gP,
                                                  nullptr, nullptr, nullptr);

    score_softmax<<<BB, 256>>>(gX2e, gP, emb_e, mask, r_sp, e_sp,
                               out, out + (size_t)BB * KK, write_ent);
}

// round 11
// speedup vs baseline: 1.1550x; 1.1550x over previous
#include <cuda_runtime.h>
#include <cuda_fp16.h>
#include <math.h>
#include <stdint.h>

#define BB 2048
#define KK 256
#define AD 512
#define IN 768

// GEMM tiling: 64x64 CTA tile, 128 threads (4 warps, 32x32 each)
#define TM 64
#define TN 64
#define TKC 64                     // K-chunk (fp16 elems) = 128 B/row
#define NSTAGE 3
#define A_ST_B (TM * 128)
#define B_ST_B (TN * 128)
#define GEMM_SMEM (NSTAGE * (A_ST_B + B_ST_B))   // 49152 B

// ---------------- scratch (device globals: no allocs allowed) ----------------
// 2-term fp16 split: A-side [hi|lo], B-side [hi|hi]  (computes a . b_hi)
__device__ __half g_A1  [(size_t)BB * 1536];   // split concat(E,H,Q)
__device__ __half g_W1s [(size_t)AD * 1536];   // split W1
__device__ __half g_A2  [(size_t)BB * 1024];   // split X (G1 out)
__device__ __half g_B2p [(size_t)768 * 1024];  // G2' B: rows 0-255 = W2[256:512] split; 256-767 = W3' split
__device__ __half g_W2T2[(size_t)512 * 512];   // prep B: W2[:256,:]^T split [hi|hi] (K'=512)
__device__ __half g_Er2 [(size_t)512 * 512];   // prep A: emb_r split [hi|lo]  (K'=512)
__device__ float  g_bias2p[768];               // [0:256]=b2[256:512], [256:768]=bias3
__device__ float  g_X2e[(size_t)BB * 256];     // X2[:, 256:512] fp32
__device__ float  g_P  [(size_t)BB * 512];     // P = X @ W3'^T + bias3

// ---------------- helpers ----------------
__device__ __forceinline__ uint32_t smem_u32(const void* p) {
    uint32_t a;
    asm("{ .reg .u64 t; cvta.to.shared.u64 t, %1; cvt.u32.u64 %0, t; }" : "=r"(a) : "l"(p));
    return a;
}
#define CP_ASYNC16(dst, src) \
    asm volatile("cp.async.cg.shared.global [%0], [%1], 16;" :: "r"(dst), "l"(src) : "memory")
#define CP_COMMIT()  asm volatile("cp.async.commit_group;" ::: "memory")
#define CP_WAIT(n)   asm volatile("cp.async.wait_group %0;" :: "n"(n) : "memory")

__device__ __forceinline__ void ldsm_x4(uint32_t* r, uint32_t addr) {
    asm volatile("ldmatrix.sync.aligned.m8n8.x4.shared.b16 {%0,%1,%2,%3}, [%4];"
                 : "=r"(r[0]), "=r"(r[1]), "=r"(r[2]), "=r"(r[3]) : "r"(addr));
}
__device__ __forceinline__ void mma16816(float* c, const uint32_t* a, const uint32_t* b) {
    asm volatile(
        "mma.sync.aligned.m16n8k16.row.col.f32.f16.f16.f32 "
        "{%0,%1,%2,%3}, {%4,%5,%6,%7}, {%8,%9}, {%0,%1,%2,%3};"
        : "+f"(c[0]), "+f"(c[1]), "+f"(c[2]), "+f"(c[3])
        : "r"(a[0]), "r"(a[1]), "r"(a[2]), "r"(a[3]), "r"(b[0]), "r"(b[1]));
}

__device__ __forceinline__ uint32_t swz(int row, int seg) {
    return (uint32_t)(row * 128 + ((seg ^ (row & 7)) << 4));
}

__device__ __forceinline__ void split_store_A(float4 v, __half* d, int Koff) {
    __align__(8) __half hh[4], ll[4];
    hh[0] = __float2half_rn(v.x); ll[0] = __float2half_rn(v.x - __half2float(hh[0]));
    hh[1] = __float2half_rn(v.y); ll[1] = __float2half_rn(v.y - __half2float(hh[1]));
    hh[2] = __float2half_rn(v.z); ll[2] = __float2half_rn(v.z - __half2float(hh[2]));
    hh[3] = __float2half_rn(v.w); ll[3] = __float2half_rn(v.w - __half2float(hh[3]));
    *(uint2*)d          = *(uint2*)hh;
    *(uint2*)(d + Koff) = *(uint2*)ll;
}
__device__ __forceinline__ void split_store_B(float4 v, __half* d, int Koff) {
    __align__(8) __half hh[4];
    hh[0] = __float2half_rn(v.x); hh[1] = __float2half_rn(v.y);
    hh[2] = __float2half_rn(v.z); hh[3] = __float2half_rn(v.w);
    *(uint2*)d          = *(uint2*)hh;
    *(uint2*)(d + Koff) = *(uint2*)hh;
}

// ---------------- fused conversion kernel ----------------
#define QR0 (BB * IN / 4)            // 393216
#define QR1 (QR0 + 512 * 768 / 4)    // 491520
#define QR2 (QR1 + 256 * 512 / 4)    // 524288
#define QR3 (QR2 + 512 * 64)         // 557056
#define QR4 (QR3 + 512 * 64)         // 589824
#define QTOT (QR4 + 64)              // 589888

__global__ __launch_bounds__(256) void conv_all(
    const float* __restrict__ E, const float* __restrict__ H, const float* __restrict__ Qm,
    const float* __restrict__ W1, const float* __restrict__ W2, const float* __restrict__ emb_r,
    const float* __restrict__ b2,
    __half* __restrict__ A1, __half* __restrict__ W1s, __half* __restrict__ B2p,
    __half* __restrict__ W2T2, __half* __restrict__ Er2, float* __restrict__ bias2p)
{
    const int q = blockIdx.x * 256 + threadIdx.x;
    if (q >= QTOT) return;
    if (q < QR0) {
        const int m = q / 192, c = (q % 192) * 4;
        const float* src = (c < 256) ? (E + m * 256 + c)
                         : (c < 512) ? (H + m * 256 + (c - 256))
                                     : (Qm + m * 256 + (c - 512));
        float4 v = *(const float4*)src;
        split_store_A(v, A1 + (size_t)m * 1536 + c, 768);
    } else if (q < QR1) {
        const int q2 = q - QR0;
        const int n = q2 / 192, k = (q2 % 192) * 4;
        float4 v = *(const float4*)(W1 + (size_t)n * 768 + k);
        split_store_B(v, W1s + (size_t)n * 1536 + k, 768);
    } else if (q < QR2) {
        const int q2 = q - QR1;
        const int n = q2 >> 7, k = (q2 & 127) * 4;           // n 0..255 -> W2 row 256+n
        float4 v = *(const float4*)(W2 + (size_t)(256 + n) * 512 + k);
        split_store_B(v, B2p + (size_t)n * 1024 + k, 512);
    } else if (q < QR3) {
        const int q2 = q - QR2;
        const int d = q2 >> 6, c0 = (q2 & 63) * 4;           // W2T2[d, c] = W2[c, d], c<256
        float4 v;
        v.x = W2[(size_t)(c0 + 0) * 512 + d];
        v.y = W2[(size_t)(c0 + 1) * 512 + d];
        v.z = W2[(size_t)(c0 + 2) * 512 + d];
        v.w = W2[(size_t)(c0 + 3) * 512 + d];
        split_store_B(v, W2T2 + (size_t)d * 512 + c0, 256);
    } else if (q < QR4) {
        const int q2 = q - QR3;
        const int n = q2 >> 6, k = (q2 & 63) * 4;            // emb_r rows, pad >=500
        float4 v = make_float4(0.f, 0.f, 0.f, 0.f);
        if (n < 500) v = *(const float4*)(emb_r + (size_t)n * 256 + k);
        split_store_A(v, Er2 + (size_t)n * 512 + k, 256);
    } else {
        const int q2 = q - QR4;                               // 64 quads of b2[256:512]
        float4 v = *(const float4*)(b2 + 256 + q2 * 4);
        *(float4*)(bias2p + q2 * 4) = v;
    }
}

// ---------------- combined G1 + prep GEMM (one launch, 320 CTAs) ----------------
// bid < 256:  G1   X = relu(A1 @ W1^T + b1) -> A-split g_A2        (ldk 1536, 24 chunks)
// bid >= 256: prep W3' = Er2 @ W2T2^T -> B-split g_B2p rows 256+   (ldk 512,  8 chunks)
//             n0==0 CTAs also compute bias3.
__global__ __launch_bounds__(128) void gemm_g1p(
    const __half* __restrict__ A1, const __half* __restrict__ W1s,
    const float* __restrict__ b1, __half* __restrict__ A2out,
    const __half* __restrict__ Er2, const __half* __restrict__ W2T2,
    __half* __restrict__ B2pout,
    const float* __restrict__ erf, const float* __restrict__ b2f,
    float* __restrict__ bias3out)
{
    extern __shared__ __half sm[];
    const uint32_t smA = smem_u32(sm);
    const uint32_t smB = smA + NSTAGE * A_ST_B;

    const int bid = blockIdx.x;
    const int t = threadIdx.x;
    const int warp = t >> 5, lane = t & 31;

    int mode, m0, n0, ldk, nchunks;
    const __half *A, *Bm;
    if (bid < 256) {
        mode = 0; m0 = (bid & 31) * 64; n0 = (bid >> 5) * 64;
        A = A1; Bm = W1s; ldk = 1536; nchunks = 24;
    } else {
        const int pb = bid - 256;
        mode = 3; m0 = (pb & 7) * 64; n0 = (pb >> 3) * 64;
        A = Er2; Bm = W2T2; ldk = 512; nchunks = 8;
    }

    const int wm = (warp >> 1) * 32;
    const int wn = (warp & 1) * 32;
    const int rA  = lane & 15;
    const int sA8 = (lane >> 4);
    const int rB  = (lane & 7) + ((lane >> 4) & 1) * 8;
    const int sB8 = ((lane >> 3) & 1);

    float acc[2][4][4] = {};

    auto load_stage = [&](int s, int chunk) {
        const size_t k0 = (size_t)chunk * TKC;
        const uint32_t dA = smA + s * A_ST_B;
        const uint32_t dB = smB + s * B_ST_B;
        #pragma unroll
        for (int i = 0; i < 4; i++) {
            int v = t + i * 128;
            int row = v >> 3, seg = v & 7;
            CP_ASYNC16(dA + swz(row, seg),
                       A + (size_t)(m0 + row) * ldk + k0 + seg * 8);
        }
        #pragma unroll
        for (int i = 0; i < 4; i++) {
            int v = t + i * 128;
            int row = v >> 3, seg = v & 7;
            CP_ASYNC16(dB + swz(row, seg),
                       Bm + (size_t)(n0 + row) * ldk + k0 + seg * 8);
        }
        CP_COMMIT();
    };

    load_stage(0, 0);
    load_stage(1, 1);

    for (int i = 0; i < nchunks; i++) {
        CP_WAIT(1);
        __syncthreads();
        if (i + 2 < nchunks) load_stage((i + 2) % NSTAGE, i + 2);
        else CP_COMMIT();

        const uint32_t sAst = smA + (i % NSTAGE) * A_ST_B;
        const uint32_t sBst = smB + (i % NSTAGE) * B_ST_B;
        #pragma unroll
        for (int ks = 0; ks < 4; ks++) {
            uint32_t a0[4], a1[4], b0[4], b1[4];
            const int segK = ks * 2;
            ldsm_x4(a0, sAst + swz(wm +      rA, segK + sA8));
            ldsm_x4(a1, sAst + swz(wm + 16 + rA, segK + sA8));
            ldsm_x4(b0, sBst + swz(wn +      rB, segK + sB8));
            ldsm_x4(b1, sBst + swz(wn + 16 + rB, segK + sB8));
            #pragma unroll
            for (int mi = 0; mi < 2; mi++) {
                const uint32_t* aa = mi ? a1 : a0;
                mma16816(acc[mi][0], aa, b0 + 0);
                mma16816(acc[mi][1], aa, b0 + 2);
                mma16816(acc[mi][2], aa, b1 + 0);
                mma16816(acc[mi][3], aa, b1 + 2);
            }
        }
    }

    // epilogue
    #pragma unroll
    for (int mi = 0; mi < 2; mi++) {
        #pragma unroll
        for (int h = 0; h < 2; h++) {
            const int row = m0 + wm + 16 * mi + 8 * h + (lane >> 2);
            #pragma unroll
            for (int j = 0; j < 4; j++) {
                const int col = n0 + wn + 8 * j + 2 * (lane & 3);
                float v0 = acc[mi][j][2 * h];
                float v1 = acc[mi][j][2 * h + 1];
                if (mode == 0) {
                    v0 = fmaxf(v0 + __ldg(&b1[col]), 0.0f);
                    v1 = fmaxf(v1 + __ldg(&b1[col + 1]), 0.0f);
                    __half h0 = __float2half_rn(v0);
                    __half h1 = __float2half_rn(v1);
                    __half l0 = __float2half_rn(v0 - __half2float(h0));
                    __half l1 = __float2half_rn(v1 - __half2float(h1));
                    __half2 hh; hh.x = h0; hh.y = h1;
                    __half2 ll; ll.x = l0; ll.y = l1;
                    __half* r0 = A2out + (size_t)row * 1024 + col;
                    *(__half2*)(r0)       = hh;
                    *(__half2*)(r0 + 512) = ll;
                } else {
                    __half2 hh;
                    hh.x = __float2half_rn(v0);
                    hh.y = __float2half_rn(v1);
                    __half* r0 = B2pout + (size_t)(256 + row) * 1024 + col;
                    *(__half2*)(r0)       = hh;
                    *(__half2*)(r0 + 512) = hh;
                }
            }
        }
    }

    if (mode == 3 && n0 == 0) {       // bias3[j] = <emb_r[j,:256], b2[:256]>
        const int j = m0 + (t >> 1);
        const int half = t & 1;
        float s = 0.0f;
        if (j < 500) {
            const float* er = erf + (size_t)j * 256 + half * 128;
            const float* bb = b2f + half * 128;
            #pragma unroll 4
            for (int c = 0; c < 128; c++) s += er[c] * bb[c];
        }
        s += __shfl_xor_sync(0xFFFFFFFFu, s, 1);
        if (half == 0) bias3out[256 + j] = (j < 500) ? s : 0.0f;
    }
}

// ---------------- G2' GEMM ----------------
// [X2e | P] = X @ [W2[256:]; W3']^T + bias2p ; cols<256 -> g_X2e, cols>=256 -> g_P
__global__ __launch_bounds__(128) void gemm_g2(
    const __half* __restrict__ A, const __half* __restrict__ Bm,
    const float* __restrict__ bias,
    float* __restrict__ outf, float* __restrict__ outf2)
{
    extern __shared__ __half sm[];
    const uint32_t smA = smem_u32(sm);
    const uint32_t smB = smA + NSTAGE * A_ST_B;

    const int t = threadIdx.x;
    const int warp = t >> 5, lane = t & 31;
    const int m0 = blockIdx.x * TM;
    const int n0 = blockIdx.y * TN;
    const int ldk = 1024, nchunks = 16;
    const int wm = (warp >> 1) * 32;
    const int wn = (warp & 1) * 32;

    const int rA  = lane & 15;
    const int sA8 = (lane >> 4);
    const int rB  = (lane & 7) + ((lane >> 4) & 1) * 8;
    const int sB8 = ((lane >> 3) & 1);

    float acc[2][4][4] = {};

    auto load_stage = [&](int s, int chunk) {
        const size_t k0 = (size_t)chunk * TKC;
        const uint32_t dA = smA + s * A_ST_B;
        const uint32_t dB = smB + s * B_ST_B;
        #pragma unroll
        for (int i = 0; i < 4; i++) {
            int v = t + i * 128;
            int row = v >> 3, seg = v & 7;
            CP_ASYNC16(dA + swz(row, seg),
                       A + (size_t)(m0 + row) * ldk + k0 + seg * 8);
        }
        #pragma unroll
        for (int i = 0; i < 4; i++) {
            int v = t + i * 128;
            int row = v >> 3, seg = v & 7;
            CP_ASYNC16(dB + swz(row, seg),
                       Bm + (size_t)(n0 + row) * ldk + k0 + seg * 8);
        }
        CP_COMMIT();
    };

    load_stage(0, 0);
    load_stage(1, 1);

    for (int i = 0; i < nchunks; i++) {
        CP_WAIT(1);
        __syncthreads();
        if (i + 2 < nchunks) load_stage((i + 2) % NSTAGE, i + 2);
        else CP_COMMIT();

        const uint32_t sAst = smA + (i % NSTAGE) * A_ST_B;
        const uint32_t sBst = smB + (i % NSTAGE) * B_ST_B;
        #pragma unroll
        for (int ks = 0; ks < 4; ks++) {
            uint32_t a0[4], a1[4], b0[4], b1[4];
            const int segK = ks * 2;
            ldsm_x4(a0, sAst + swz(wm +      rA, segK + sA8));
            ldsm_x4(a1, sAst + swz(wm + 16 + rA, segK + sA8));
            ldsm_x4(b0, sBst + swz(wn +      rB, segK + sB8));
            ldsm_x4(b1, sBst + swz(wn + 16 + rB, segK + sB8));
            #pragma unroll
            for (int mi = 0; mi < 2; mi++) {
                const uint32_t* aa = mi ? a1 : a0;
                mma16816(acc[mi][0], aa, b0 + 0);
                mma16816(acc[mi][1], aa, b0 + 2);
                mma16816(acc[mi][2], aa, b1 + 0);
                mma16816(acc[mi][3], aa, b1 + 2);
            }
        }
    }

    #pragma unroll
    for (int mi = 0; mi < 2; mi++) {
        #pragma unroll
        for (int h = 0; h < 2; h++) {
            const int row = m0 + wm + 16 * mi + 8 * h + (lane >> 2);
            #pragma unroll
            for (int j = 0; j < 4; j++) {
                const int col = n0 + wn + 8 * j + 2 * (lane & 3);
                float v0 = acc[mi][j][2 * h] + __ldg(&bias[col]);
                float v1 = acc[mi][j][2 * h + 1] + __ldg(&bias[col + 1]);
                if (col < 256)
                    *(float2*)(outf + (size_t)row * 256 + col) = make_float2(v0, v1);
                else
                    *(float2*)(outf2 + (size_t)row * 512 + (col - 256)) = make_float2(v0, v1);
            }
        }
    }
}

// ---------------- score + softmax + entropy (round-8 proven gather) ----------------
__global__ __launch_bounds__(256) void score_softmax(
    const float* __restrict__ X2e, const float* __restrict__ P,
    const float* __restrict__ emb_e, const float* __restrict__ mask,
    const int* __restrict__ r_space, const int* __restrict__ e_space,
    float* __restrict__ out_dist, float* __restrict__ out_ent, int write_ent)
{
    const int b = blockIdx.x;
    __shared__ float x2e[256];
    __shared__ float sc[KK];
    __shared__ float red1[8], red2[8], red3[8];
    const int t = threadIdx.x;
    const int warp = t >> 5, lane = t & 31;

    x2e[t] = X2e[b * 256 + t];
    const int   kidx = warp * 32 + lane;
    const int   eall = e_space[b * KK + kidx];
    const float mval = mask[b * KK + kidx];
    const unsigned validb = __ballot_sync(0xFFFFFFFFu, mval != 0.0f);
    __syncthreads();

    const float4 xa = *(const float4*)&x2e[lane * 4];
    const float4 xb = *(const float4*)&x2e[lane * 4 + 128];

    for (int i = 0; i < 32; i++) {
        const int k = warp * 32 + i;
        if ((validb >> i) & 1u) {
            const int e = __shfl_sync(0xFFFFFFFFu, eall, i);
            const float4* er = (const float4*)(emb_e + (size_t)e * 256);
            const float4 v0 = er[lane];
            const float4 v1 = er[lane + 32];
            float s = v0.x * xa.x + v0.y * xa.y + v0.z * xa.z + v0.w * xa.w
                    + v1.x * xb.x + v1.y * xb.y + v1.z * xb.z + v1.w * xb.w;
            #pragma unroll
            for (int o = 16; o; o >>= 1) s += __shfl_xor_sync(0xFFFFFFFFu, s, o);
            if (lane == 0) sc[k] = s;
        } else {
            if (lane == 0) sc[k] = 0.0f;    // dot irrelevant: s = 0 + P - 1e31 -> weight 0
        }
    }
    __syncthreads();

    const int r = r_space[b * KK + t];
    float s = sc[t] + P[b * 512 + r] - (1.0f - mask[b * KK + t]) * 1e31f;

    float mx = s;
#pragma unroll
    for (int o = 16; o; o >>= 1) mx = fmaxf(mx, __shfl_xor_sync(0xFFFFFFFFu, mx, o));
    if (lane == 0) red1[warp] = mx;
    __syncthreads();
    float bm = red1[0];
#pragma unroll
    for (int w = 1; w < 8; w++) bm = fmaxf(bm, red1[w]);

    const float p = expf(s - bm);
    float sum = p;
#pragma unroll
    for (int o = 16; o; o >>= 1) sum += __shfl_xor_sync(0xFFFFFFFFu, sum, o);
    if (lane == 0) red2[warp] = sum;
    __syncthreads();
    float bs = 0.f;
#pragma unroll
    for (int w = 0; w < 8; w++) bs += red2[w];

    const float dist = p / bs;
    out_dist[b * KK + t] = dist;

    float es = -dist * logf(dist + 1e-20f);
#pragma unroll
    for (int o = 16; o; o >>= 1) es += __shfl_xor_sync(0xFFFFFFFFu, es, o);
    if (lane == 0) red3[warp] = es;
    __syncthreads();
    if (t == 0 && write_ent) {
        float tot = 0.f;
#pragma unroll
        for (int w = 0; w < 8; w++) tot += red3[w];
        out_ent[b] = tot;
    }
}

// ---------------- launcher ----------------
extern "C" void kernel_launch(void* const* d_in, const int* in_sizes, int n_in,
                              void* d_out, int out_size)
{
    const float* E     = (const float*)d_in[0];
    const float* H     = (const float*)d_in[1];
    const float* Q     = (const float*)d_in[2];
    const float* W1    = (const float*)d_in[3];
    const float* b1    = (const float*)d_in[4];
    const float* W2    = (const float*)d_in[5];
    const float* b2    = (const float*)d_in[6];
    const float* emb_r = (const float*)d_in[7];
    const float* emb_e = (const float*)d_in[8];
    const float* mask  = (const float*)d_in[9];
    const int*   r_sp  = (const int*)d_in[10];
    const int*   e_sp  = (const int*)d_in[11];
    float* out = (float*)d_out;

    __half *gA1, *gW1s, *gA2, *gB2p, *gW2T2, *gEr2;
    float *gX2e, *gP, *gbias2p;
    cudaGetSymbolAddress((void**)&gA1,    g_A1);
    cudaGetSymbolAddress((void**)&gW1s,   g_W1s);
    cudaGetSymbolAddress((void**)&gA2,    g_A2);
    cudaGetSymbolAddress((void**)&gB2p,   g_B2p);
    cudaGetSymbolAddress((void**)&gW2T2,  g_W2T2);
    cudaGetSymbolAddress((void**)&gEr2,   g_Er2);
    cudaGetSymbolAddress((void**)&gX2e,   g_X2e);
    cudaGetSymbolAddress((void**)&gP,     g_P);
    cudaGetSymbolAddress((void**)&gbias2p, g_bias2p);

    cudaFuncSetAttribute(gemm_g1p, cudaFuncAttributeMaxDynamicSharedMemorySize, GEMM_SMEM);
    cudaFuncSetAttribute(gemm_g2,  cudaFuncAttributeMaxDynamicSharedMemorySize, GEMM_SMEM);

    const int write_ent = (out_size >= BB * KK + BB) ? 1 : 0;

    conv_all<<<(QTOT + 255) / 256, 256>>>(E, H, Q, W1, W2, emb_r, b2,
                                          gA1, gW1s, gB2p, gW2T2, gEr2, gbias2p);

    // G1 (256 CTAs) + prep W3' (64 CTAs) in one launch
    gemm_g1p<<<320, 128, GEMM_SMEM>>>(gA1, gW1s, b1, gA2,
                                      gEr2, gW2T2, gB2p,
                                      emb_r, b2, gbias2p);

    // G2': [X2e | P] = X @ [W2[256:]; W3']^T + bias2p
    gemm_g2<<<dim3(32, 12), 128, GEMM_SMEM>>>(gA2, gB2p, gbias2p, gX2e, gP);

    score_softmax<<<BB, 256>>>(gX2e, gP, emb_e, mask, r_sp, e_sp,
                               out, out + (size_t)BB * KK, write_ent);
}